// round 2
// baseline (speedup 1.0000x reference)
#include <cuda_runtime.h>
#include <cuda_bf16.h>
#include <math.h>
#include <float.h>

#define NDATA 200000
#define BATCH 256
#define BIT   64
#define TOPF  20
#define KNEG  2500
#define RANKK 20000              /* N_DATA - HIGH, 0-based ascending rank of kth */
#define THRESH 0.3f
#define TINV  (1.0f/7.2f)        /* 1 / (0.9*sqrt(64)) */
#define NT    1024
#define NBIN  1024
#define CAP   4096
#define NWORD (NDATA/32)         /* 6250 */

/* ------------------------------------------------------------------ scratch */
__device__ float g_sim[(long long)BATCH * NDATA];   /* [B][N] */
__device__ float g_fsum[BATCH * BIT];
__device__ float g_f1[BATCH * BIT];
__device__ float g_newf[BATCH * BIT];
__device__ float g_loss[BATCH];

/* ------------------------------------------------------------------ fuse */
__global__ void k_fuse(const float* __restrict__ iA, const float* __restrict__ iB,
                       const float* __restrict__ tA, const float* __restrict__ tB) {
    int b = blockIdx.x, j = threadIdx.x;
    float ia = iA[b * BIT + j], ib = iB[b * BIT + j];
    float ta = tA[b * BIT + j], tb = tB[b * BIT + j];
    float f[4] = {(ia + ta) * 0.5f, (ia + tb) * 0.5f,
                  (ib + ta) * 0.5f, (ib + tb) * 0.5f};
    __shared__ float red[BIT];
    float fs = 0.0f;
    for (int q = 0; q < 4; q++) {
        red[j] = f[q] * f[q]; __syncthreads();
        for (int o = 32; o > 0; o >>= 1) { if (j < o) red[j] += red[j + o]; __syncthreads(); }
        float nrm = sqrtf(red[0]);
        __syncthreads();
        float nf = f[q] / nrm;
        fs += nf;
        if (q == 0) { g_f1[b * BIT + j] = f[q]; g_newf[b * BIT + j] = nf; }
    }
    g_fsum[b * BIT + j] = fs * 0.25f;
}

/* ------------------------------------------------------------------ GEMM */
#define GI 128
#define GB 128
#define KC 16
__global__ void __launch_bounds__(256) k_gemm(const float* __restrict__ mem) {
    __shared__ float Ms[KC][GI];
    __shared__ float Fs[KC][GB];
    int i0 = blockIdx.x * GI;
    int b0 = blockIdx.y * GB;
    int tid = threadIdx.x;
    int tx = tid & 15, ty = tid >> 4;
    float acc[8][8];
#pragma unroll
    for (int r = 0; r < 8; r++)
#pragma unroll
        for (int q = 0; q < 8; q++) acc[r][q] = 0.0f;

    for (int k0 = 0; k0 < BIT; k0 += KC) {
        int k = tid & 15;
        for (int il = tid >> 4; il < GI; il += 16) {
            int gi = i0 + il;
            Ms[k][il] = (gi < NDATA) ? mem[(size_t)gi * BIT + k0 + k] : 0.0f;
        }
        for (int bl = tid >> 4; bl < GB; bl += 16)
            Fs[k][bl] = g_fsum[(b0 + bl) * BIT + k0 + k];
        __syncthreads();
#pragma unroll
        for (int kk = 0; kk < KC; kk++) {
            float mv[8], fv[8];
#pragma unroll
            for (int q = 0; q < 8; q++) mv[q] = Ms[kk][tx + q * 16];
#pragma unroll
            for (int r = 0; r < 8; r++) fv[r] = Fs[kk][ty + r * 16];
#pragma unroll
            for (int r = 0; r < 8; r++)
#pragma unroll
                for (int q = 0; q < 8; q++) acc[r][q] += fv[r] * mv[q];
        }
        __syncthreads();
    }
#pragma unroll
    for (int r = 0; r < 8; r++) {
        int gb = b0 + ty + r * 16;
#pragma unroll
        for (int q = 0; q < 8; q++) {
            int gi = i0 + tx + q * 16;
            if (gi < NDATA) g_sim[(size_t)gb * NDATA + gi] = acc[r][q];
        }
    }
}

/* ------------------------------------------------------------------ helpers */
__device__ __forceinline__ int binof(float v, float lo, float invw) {
    int b = (int)((v - lo) * invw);
    return b < 0 ? 0 : (b > 1023 ? 1023 : b);
}

/* bin of v at level L of the sim chain (lo0=-1, w0=2); -1 if prefix mismatch */
__device__ __forceinline__ int level_bin_sim(float v, const int* ch, int L) {
    float lo = -1.0f, w = 2.0f;
    for (int l = 0; l < L; l++) {
        int b = binof(v, lo, 1024.0f / w);
        if (b != ch[l]) return -1;
        lo += (float)b * (w * 0.0009765625f);
        w *= 0.0009765625f;
    }
    return binof(v, lo, 1024.0f / w);
}

__device__ void scan_incl(unsigned* s) {   /* 1024 bins, 1024 threads */
    int t = threadIdx.x;
    for (int off = 1; off < NBIN; off <<= 1) {
        unsigned v = (t >= off) ? s[t - off] : 0u;
        __syncthreads();
        s[t] += v;
        __syncthreads();
    }
}

/* first bin with inclusive-cum > rank */
__device__ int find_bin(unsigned* cum, int rank, int* tmp) {
    if (threadIdx.x == 0) *tmp = 1023;
    __syncthreads();
    int c = (int)cum[threadIdx.x];
    int cp = threadIdx.x ? (int)cum[threadIdx.x - 1] : 0;
    if (c > rank && cp <= rank) *tmp = (int)threadIdx.x;
    __syncthreads();
    int r = *tmp;
    __syncthreads();
    return r;
}

__device__ int p2(int n) { int v = 1; while (v < n) v <<= 1; return v; }

__device__ void sort_f_asc(float* a, int n2) {
    for (int k = 2; k <= n2; k <<= 1)
        for (int j = k >> 1; j > 0; j >>= 1) {
            for (int t = threadIdx.x; t < n2; t += NT) {
                int p = t ^ j;
                if (p > t) {
                    float x = a[t], y = a[p];
                    bool dir = ((t & k) == 0);
                    if ((x > y) == dir) { a[t] = y; a[p] = x; }
                }
            }
            __syncthreads();
        }
}

__device__ __forceinline__ bool better(float va, int ia, float vb, int ib) {
    return va > vb || (va == vb && ia < ib);   /* value desc, index asc */
}

__device__ void sort_pair_desc(float* v, int* id, int n2) {
    for (int k = 2; k <= n2; k <<= 1)
        for (int j = k >> 1; j > 0; j >>= 1) {
            for (int t = threadIdx.x; t < n2; t += NT) {
                int p = t ^ j;
                if (p > t) {
                    float va = v[t], vb = v[p];
                    int ia = id[t], ib = id[p];
                    bool dir = ((t & k) == 0);
                    if (better(vb, ib, va, ia) == dir) {
                        v[t] = vb; v[p] = va; id[t] = ib; id[p] = ia;
                    }
                }
            }
            __syncthreads();
        }
}

__device__ float block_sum(float v, float* red) {
    int t = threadIdx.x;
    red[t] = v; __syncthreads();
    for (int o = 512; o > 0; o >>= 1) { if (t < o) red[t] += red[t + o]; __syncthreads(); }
    return red[0];
}

/* dot(sign(mem[i]), f1) — mem rows are +-0.125, never 0 */
__device__ __forceinline__ float dot_sign(const float* __restrict__ mem, int i,
                                          const float* __restrict__ f1s) {
    const float4* mp = reinterpret_cast<const float4*>(mem) + (size_t)i * 16;
    float s = 0.0f;
#pragma unroll
    for (int q = 0; q < 16; q++) {
        float4 m = mp[q];
        s += __int_as_float(__float_as_int(f1s[4 * q + 0]) ^ (__float_as_int(m.x) & 0x80000000));
        s += __int_as_float(__float_as_int(f1s[4 * q + 1]) ^ (__float_as_int(m.y) & 0x80000000));
        s += __int_as_float(__float_as_int(f1s[4 * q + 2]) ^ (__float_as_int(m.z) & 0x80000000));
        s += __int_as_float(__float_as_int(f1s[4 * q + 3]) ^ (__float_as_int(m.w) & 0x80000000));
    }
    return s;
}

/* ---------------- shared layout (uint units) ---------------- */
#define OF_HIST 0
#define OF_BM   1024
#define OF_BUFV 7274
#define OF_BUFI 11370
#define OF_RED  15466
#define OF_F1   16490
#define OF_TOPV 16554
#define OF_TOPI 16574
#define OF_EXCL 16594
#define OF_CHK  16618
#define OF_SCAL 16622
#define OF_FSC  16638
#define SMEM_U  16648
#define SMEM_BYTES (SMEM_U * 4)

/* ------------------------------------------------------------------ per-row */
__global__ void __launch_bounds__(NT, 1) k_row(const float* __restrict__ mem,
                                               const float* __restrict__ ru_all,
                                               const int* __restrict__ bidx) {
    extern __shared__ unsigned sh[];
    unsigned* hist  = sh + OF_HIST;
    unsigned* bm    = sh + OF_BM;
    float*    bufV  = (float*)(sh + OF_BUFV);
    int*      bufI  = (int*)(sh + OF_BUFI);
    float*    red   = (float*)(sh + OF_RED);
    float*    f1s   = (float*)(sh + OF_F1);
    float*    topvS = (float*)(sh + OF_TOPV);
    int*      topiS = (int*)(sh + OF_TOPI);
    int*      exclS = (int*)(sh + OF_EXCL);
    int*      chK   = (int*)(sh + OF_CHK);
    int*      scal  = (int*)(sh + OF_SCAL);
    float*    fsc   = (float*)(sh + OF_FSC);

    int b = blockIdx.x, tid = threadIdx.x;
    const float* S  = g_sim + (size_t)b * NDATA;
    const float* RU = ru_all + (size_t)b * NDATA;
    int pos = bidx[b];

    if (tid < BIT) f1s[tid] = g_f1[b * BIT + tid];

    /* ---- Phase 1: level-0 sim histogram, find kth bin and top-20 bin ---- */
    hist[tid] = 0; __syncthreads();
    for (int i = tid; i < NDATA; i += NT)
        atomicAdd(&hist[binof(S[i], -1.0f, 512.0f)], 1u);
    __syncthreads();
    scan_incl(hist);
    int jbk = find_bin(hist, RANKK, &scal[8]);
    int jbt = find_bin(hist, NDATA - TOPF, &scal[8]);
    int belowk = jbk ? (int)hist[jbk - 1] : 0;
    int cntk = (int)hist[jbk] - belowk;
    int rkin = RANKK - belowk;
    if (tid == 0) chK[0] = jbk;
    __syncthreads();

    /* ---- Phase 2: refine kth bin if overfull (rare) ---- */
    int depth = 0;
    while (cntk > CAP && depth < 2) {
        depth++;
        hist[tid] = 0; __syncthreads();
        for (int i = tid; i < NDATA; i += NT) {
            int bb = level_bin_sim(S[i], chK, depth);
            if (bb >= 0) atomicAdd(&hist[bb], 1u);
        }
        __syncthreads();
        scan_incl(hist);
        int jb = find_bin(hist, rkin, &scal[8]);
        int below = jb ? (int)hist[jb - 1] : 0;
        cntk = (int)hist[jb] - below;
        rkin -= below;
        if (tid == 0) chK[depth] = jb;
        __syncthreads();
    }

    /* ---- Phase 3: collect kth bin, exact kth value ---- */
    if (tid == 0) scal[1] = 0;
    __syncthreads();
    for (int i = tid; i < NDATA; i += NT) {
        float v = S[i];
        if (level_bin_sim(v, chK, depth) == chK[depth]) {
            int p = atomicAdd(&scal[1], 1);
            if (p < CAP) bufV[p] = v;
        }
    }
    __syncthreads();
    int nc = min(scal[1], CAP);
    int n2 = p2(nc);
    for (int t = tid; t < n2; t += NT) if (t >= nc) bufV[t] = FLT_MAX;
    __syncthreads();
    sort_f_asc(bufV, n2);
    int rk = min(rkin, nc - 1);
    float kth = bufV[rk];
    __syncthreads();

    /* ---- Phase 4: collect top region (bins >= jbt), exact top-20 ---- */
    if (tid == 0) scal[1] = 0;
    __syncthreads();
    for (int i = tid; i < NDATA; i += NT) {
        float v = S[i];
        if (binof(v, -1.0f, 512.0f) >= jbt) {
            int p = atomicAdd(&scal[1], 1);
            if (p < CAP) { bufV[p] = v; bufI[p] = i; }
        }
    }
    __syncthreads();
    nc = min(scal[1], CAP);
    n2 = p2(nc);
    for (int t = tid; t < n2; t += NT)
        if (t >= nc) { bufV[t] = -FLT_MAX; bufI[t] = 0x7FFFFFFF; }
    __syncthreads();
    sort_pair_desc(bufV, bufI, n2);
    if (tid < TOPF) {
        if (tid < nc) { topvS[tid] = bufV[tid]; topiS[tid] = bufI[tid]; }
        else          { topvS[tid] = -FLT_MAX;  topiS[tid] = -1; }
    }
    __syncthreads();

    /* ---- Phase 5: fnp/pos dots, exclusions ---- */
    if (tid <= TOPF) {
        int idx = (tid < TOPF) ? topiS[tid] : pos;
        red[tid] = (idx >= 0) ? dot_sign(mem, idx, f1s) * TINV : 0.0f;
    }
    __syncthreads();
    if (tid == 0) {
        float pe = expf(red[TOPF]);
        float fs = 0.0f; int nf = 0, ne = 0;
        for (int t = 0; t < TOPF; t++) {
            bool val = (topvS[t] > THRESH) && (topiS[t] != pos) && (topiS[t] >= 0);
            if (val) { nf++; float d = red[t]; fs += d * expf(d); exclS[ne++] = topiS[t]; }
        }
        exclS[ne++] = pos;
        scal[2] = ne; scal[3] = nf;
        fsc[0] = pe; fsc[1] = fs;
    }
    __syncthreads();

    /* ---- Phase 6: candidate bitmap + ru histogram ---- */
    hist[tid] = 0; __syncthreads();
    for (int w = tid; w < NWORD; w += NT) {
        int base = w * 32;
        unsigned word = 0;
        for (int q = 0; q < 32; q++) {
            int i = base + q;
            float s = S[i];
            if (s >= kth) {
                word |= 1u << q;
                atomicAdd(&hist[binof(RU[i], 0.0f, 1024.0f)], 1u);
            }
        }
        bm[w] = word;
    }
    __syncthreads();
    if (tid == 0) {   /* remove excluded indices from candidates */
        int ne = scal[2];
        for (int e = 0; e < ne; e++) {
            int i = exclS[e];
            if (S[i] >= kth) {
                bm[i >> 5] &= ~(1u << (i & 31));
                hist[binof(RU[i], 0.0f, 1024.0f)]--;
            }
        }
    }
    __syncthreads();
    scan_incl(hist);
    int C = (int)hist[1023];
    int jbr = find_bin(hist, C - KNEG, &scal[8]);
    int above = C - (int)hist[jbr];
    int m = KNEG - above;

    /* ---- Phase 7: negative sum ---- */
    if (tid == 0) scal[1] = 0;
    __syncthreads();
    float lsum = 0.0f;
    for (int w = tid; w < NWORD; w += NT) {
        unsigned word = bm[w];
        int base = w * 32;
        while (word) {
            int q = __ffs((int)word) - 1;
            word &= word - 1;
            int i = base + q;
            float r = RU[i];
            int rb = binof(r, 0.0f, 1024.0f);
            if (rb > jbr) {
                lsum += expf(dot_sign(mem, i, f1s) * TINV);
            } else if (rb == jbr) {
                int p = atomicAdd(&scal[1], 1);
                if (p < CAP) { bufV[p] = r; bufI[p] = i; }
            }
        }
    }
    __syncthreads();
    nc = min(scal[1], CAP);
    n2 = p2(nc);
    for (int t = tid; t < n2; t += NT)
        if (t >= nc) { bufV[t] = -FLT_MAX; bufI[t] = 0x7FFFFFFF; }
    __syncthreads();
    sort_pair_desc(bufV, bufI, n2);
    int mm = min(m, nc);
    for (int t = tid; t < mm; t += NT)
        lsum += expf(dot_sign(mem, bufI[t], f1s) * TINV);
    float dn = block_sum(lsum, red);
    if (tid == 0) {
        float den = dn + fsc[0];
        float num = fsc[0] + fsc[1];
        g_loss[b] = -logf(num / den) / (1.0f + (float)scal[3]);
    }
}

/* ------------------------------------------------------------------ epilogue */
__global__ void k_loss(float* __restrict__ out) {
    __shared__ float red[BATCH];
    int t = threadIdx.x;
    red[t] = g_loss[t]; __syncthreads();
    for (int o = 128; o > 0; o >>= 1) { if (t < o) red[t] += red[t + o]; __syncthreads(); }
    if (t == 0) out[0] = red[0] * (1.0f / BATCH);
}

__global__ void k_update(const float* __restrict__ mem, const int* __restrict__ bidx,
                         float* __restrict__ out) {
    int b = blockIdx.x, j = threadIdx.x;
    __shared__ int skip, idx;
    __shared__ float red[BIT];
    if (j == 0) {
        int id = bidx[b];
        idx = id;
        int s = 0;
        for (int b2 = b + 1; b2 < BATCH; b2++) if (bidx[b2] == id) { s = 1; break; }
        skip = s;
    }
    __syncthreads();
    if (skip) return;
    float v = mem[(size_t)idx * BIT + j] * 0.4f + g_newf[b * BIT + j] * 0.6f;
    red[j] = v * v; __syncthreads();
    for (int o = 32; o > 0; o >>= 1) { if (j < o) red[j] += red[j + o]; __syncthreads(); }
    out[1 + (size_t)idx * BIT + j] = v / sqrtf(red[0]);
}

/* ------------------------------------------------------------------ launch */
extern "C" void kernel_launch(void* const* d_in, const int* in_sizes, int n_in,
                              void* d_out, int out_size) {
    const float* iA  = (const float*)d_in[0];
    const float* iB  = (const float*)d_in[1];
    const float* tA  = (const float*)d_in[2];
    const float* tB  = (const float*)d_in[3];
    const float* mem = (const float*)d_in[4];
    const float* ru  = (const float*)d_in[5];
    const int*   bidx= (const int*)d_in[6];
    float* out = (float*)d_out;

    k_fuse<<<BATCH, BIT>>>(iA, iB, tA, tB);
    dim3 gg((NDATA + GI - 1) / GI, BATCH / GB);
    k_gemm<<<gg, 256>>>(mem);
    cudaFuncSetAttribute((const void*)k_row, cudaFuncAttributeMaxDynamicSharedMemorySize,
                         SMEM_BYTES);
    k_row<<<BATCH, NT, SMEM_BYTES>>>(mem, ru, bidx);
    k_loss<<<1, BATCH>>>(out);
    cudaMemcpyAsync(out + 1, mem, (size_t)NDATA * BIT * sizeof(float),
                    cudaMemcpyDeviceToDevice, 0);
    k_update<<<BATCH, BIT>>>(mem, bidx, out);
}